// round 10
// baseline (speedup 1.0000x reference)
#include <cuda_runtime.h>
#include <math.h>

// ---------------------------------------------------------------------------
// Problem constants
// ---------------------------------------------------------------------------
#define NL 8
#define NP 512
#define NR (NL*NP)          // 4096 rays
#define NC 64               // coarse samples
#define NF 128              // fine samples
#define NA (NC+NF)          // 192 all samples
#define HID 128
#define TILE 128            // samples per MLP tile
#define BUFPAD 132          // padded row length of activation buffer (16B aligned rows)

// scratch (device globals; no allocation allowed)
__device__ float g_u0[NR*HID];       // W0^T pt + b0 per ray
__device__ float g_v0[NR*HID];       // W0^T dir per ray
__device__ float g_sdfc[NR*NC];      // coarse sdf
__device__ float g_dall[NR*NA];      // sorted merged depths
__device__ float g_sdfa[NR*NA];      // fine-pass sdf

// ---------------------------------------------------------------------------
// f32x2 packed helpers (Blackwell FFMA2 — 2x fp32 fma throughput)
// ---------------------------------------------------------------------------
__device__ __forceinline__ unsigned long long pack2(float x) {
    unsigned long long r;
    asm("mov.b64 %0, {%1, %1};" : "=l"(r) : "f"(x));
    return r;
}
__device__ __forceinline__ void ffma2(unsigned long long& d,
                                      unsigned long long a,
                                      unsigned long long b) {
    asm("fma.rn.f32x2 %0, %1, %2, %0;" : "+l"(d) : "l"(a), "l"(b));
}
__device__ __forceinline__ float2 unpack2(unsigned long long v) {
    float lo, hi;
    asm("mov.b64 {%0, %1}, %2;" : "=f"(lo), "=f"(hi) : "l"(v));
    return make_float2(lo, hi);
}

// ---------------------------------------------------------------------------
// K1: per-ray prep — dir normalize + fold layer0 into (u0, v0)
//     h0(sample) = relu(u0 + d * v0)
// ---------------------------------------------------------------------------
__global__ void prep_kernel(const float* __restrict__ pts,
                            const float* __restrict__ light,
                            const float* __restrict__ w0,
                            const float* __restrict__ b0) {
    int r = blockIdx.x;          // ray = l*512 + p
    int k = threadIdx.x;         // hidden unit
    int l = r >> 9, p = r & 511;
    __shared__ float sp[3], sd[3];
    if (k == 0) {
        float px = pts[p*3+0], py = pts[p*3+1], pz = pts[p*3+2];
        float dx = light[l*3+0]-px, dy = light[l*3+1]-py, dz = light[l*3+2]-pz;
        float n = sqrtf(dx*dx + dy*dy + dz*dz);
        sp[0]=px; sp[1]=py; sp[2]=pz;
        sd[0]=dx/n; sd[1]=dy/n; sd[2]=dz/n;
    }
    __syncthreads();
    float w0k = w0[k], w1k = w0[128+k], w2k = w0[256+k];
    float u0 = b0[k] + sp[0]*w0k + sp[1]*w1k + sp[2]*w2k;
    float v0 =         sd[0]*w0k + sd[1]*w1k + sd[2]*w2k;
    g_u0[r*HID + k] = u0;
    g_v0[r*HID + k] = v0;
}

// ---------------------------------------------------------------------------
// Dense 128->128 layer on a 128-sample tile (relu + bias), in-place in smem.
// buf layout: [k (128)][BUFPAD], samples contiguous in the row.
// thread (j,g): output unit j, points [g*64, g*64+64) as 32 f32x2 accs.
// ---------------------------------------------------------------------------
__device__ __forceinline__ void dense_layer(const float* __restrict__ Ws,
                                            const float* __restrict__ bs,
                                            float* __restrict__ buf,
                                            int j, int g) {
    unsigned long long acc[32];
#pragma unroll
    for (int t = 0; t < 32; ++t) acc[t] = 0ULL;

#pragma unroll 4
    for (int k = 0; k < 128; ++k) {
        unsigned long long wv = pack2(Ws[k*128 + j]);           // conflict-free LDS
        const ulonglong2* h4 =
            reinterpret_cast<const ulonglong2*>(buf + k*BUFPAD + g*64); // broadcast LDS.128
#pragma unroll
        for (int t = 0; t < 16; ++t) {
            ulonglong2 hv = h4[t];
            ffma2(acc[2*t+0], hv.x, wv);
            ffma2(acc[2*t+1], hv.y, wv);
        }
    }
    __syncthreads();   // all reads of buf done
    float bj = bs[j];
    float2* outp = reinterpret_cast<float2*>(buf + j*BUFPAD + g*64);
#pragma unroll
    for (int t = 0; t < 32; ++t) {
        float2 v = unpack2(acc[t]);
        v.x = fmaxf(v.x + bj, 0.0f);
        v.y = fmaxf(v.y + bj, 0.0f);
        outp[t] = v;
    }
    __syncthreads();   // buf now holds layer output
}

// ---------------------------------------------------------------------------
// K2/K4: fused 3-layer MLP over all samples. Persistent CTAs, weights in smem.
// COARSE: d analytic, out -> g_sdfc.  else: d from g_dall, out -> g_sdfa.
// ---------------------------------------------------------------------------
// smem floats: W1(16384) W2(16384) buf(128*132=16896) b1(128) b2(128) w3(128) d(128)
#define SMEM_FLOATS (16384*2 + 128*BUFPAD + 128*4)
#define SMEM_BYTES  (SMEM_FLOATS * 4)

template <int M, bool COARSE>
__global__ void __launch_bounds__(256, 1)
mlp_kernel(const float* __restrict__ w1, const float* __restrict__ b1,
           const float* __restrict__ w2, const float* __restrict__ b2,
           const float* __restrict__ w3, const float* __restrict__ b3) {
    extern __shared__ float sm[];
    float* W1s = sm;
    float* W2s = sm + 16384;
    float* buf = sm + 32768;
    float* b1s = sm + 32768 + 128*BUFPAD;
    float* b2s = b1s + 128;
    float* w3s = b2s + 128;
    float* d_s = w3s + 128;

    const int tid = threadIdx.x;
    const int j = tid & 127;
    const int g = tid >> 7;

    // load weights once per CTA (persistent)
    {
        const float4* s1 = reinterpret_cast<const float4*>(w1);
        const float4* s2 = reinterpret_cast<const float4*>(w2);
        float4* dd1 = reinterpret_cast<float4*>(W1s);
        float4* dd2 = reinterpret_cast<float4*>(W2s);
        for (int i = tid; i < 4096; i += 256) { dd1[i] = s1[i]; dd2[i] = s2[i]; }
        if (tid < 128) { b1s[tid] = b1[tid]; b2s[tid] = b2[tid]; w3s[tid] = w3[tid]; }
    }
    const float b3v = b3[0];
    __syncthreads();

    const int ntiles = (NR * M) / TILE;   // exact, no tail
    for (int tile = blockIdx.x; tile < ntiles; tile += gridDim.x) {
        const int s0 = tile * TILE;

        // stage depths for the tile
        if (tid < TILE) {
            int s = s0 + tid;
            float dv;
            if (COARSE) {
                int m = s & (NC - 1);
                float tt = (float)m * (1.0f / (float)NC);
                dv = 1e-3f * (1.0f - tt) + 0.5f * tt;
            } else {
                dv = g_dall[s];
            }
            d_s[tid] = dv;
        }

        // a tile spans at most 2 rays
        int ray0 = s0 / M;
        int ray1 = (s0 + TILE - 1) / M;
        int split = (ray1 == ray0) ? TILE : (ray1 * M - s0);
        float u0a = g_u0[ray0*HID + j], v0a = g_v0[ray0*HID + j];
        float u0b = g_u0[ray1*HID + j], v0b = g_v0[ray1*HID + j];
        __syncthreads();

        // h0 = relu(u0 + d*v0)
        float* myrow = buf + j*BUFPAD + g*64;
#pragma unroll 8
        for (int bb = 0; bb < 64; ++bb) {
            int b = g*64 + bb;
            float uu = (b < split) ? u0a : u0b;
            float vv = (b < split) ? v0a : v0b;
            myrow[bb] = fmaxf(fmaf(d_s[b], vv, uu), 0.0f);
        }
        __syncthreads();

        dense_layer(W1s, b1s, buf, j, g);
        dense_layer(W2s, b2s, buf, j, g);

        // layer 3: 128->1 per sample
        if (tid < TILE) {
            float a3 = 0.0f;
#pragma unroll 16
            for (int k = 0; k < 128; ++k)
                a3 = fmaf(buf[k*BUFPAD + tid], w3s[k], a3);
            float* outp = COARSE ? g_sdfc : g_sdfa;
            outp[s0 + tid] = a3 + b3v;
        }
        __syncthreads();   // protect buf before next tile's h0
    }
}

// ---------------------------------------------------------------------------
// K3: per-ray weights -> pdf sampling -> rank-sort fine -> merge with coarse
// ---------------------------------------------------------------------------
__global__ void sample_kernel(const float* __restrict__ u_in) {
    int r = blockIdx.x;
    int t = threadIdx.x;   // 64 threads
    __shared__ float sig[NC], cdf[NC], dc[NC], w63[NC-1];
    __shared__ float fval[NF], fsort[NF];

    if (t < NC) {
        float sdf = g_sdfc[r*NC + t];
        sig[t] = 1.0f / (1.0f + expf(-100.0f * sdf));
        float tt = (float)t * (1.0f / (float)NC);
        dc[t] = 1e-3f * (1.0f - tt) + 0.5f * tt;
    }
    __syncthreads();

    if (t == 0) {
        // sdf_to_w + (+1e-5) + sum (serial, 63 steps)
        float T = 1.0f, wsum = 0.0f;
        for (int i = 0; i < NC-1; ++i) {
            float a = fmaxf((sig[i] - sig[i+1]) / (sig[i] + 1e-10f), 0.0f);
            float wv = a * T + 1e-5f;
            w63[i] = wv;
            wsum += wv;
            T *= (1.0f - a + 1e-10f);
        }
        float c = 0.0f;
        cdf[0] = 0.0f;
        for (int i = 0; i < NC-1; ++i) {
            c += w63[i] / wsum;
            cdf[i+1] = c;
        }
    }
    __syncthreads();

    // inverse-CDF sampling: 2 u's per thread
    for (int q = t; q < NF; q += 64) {
        float uu = u_in[r*NF + q];
        int inds = 0;
#pragma unroll
        for (int i = 0; i < NC; ++i) inds += (uu >= cdf[i]) ? 1 : 0;
        int below = inds - 1; if (below < 0) below = 0; if (below > NC-1) below = NC-1;
        int above = inds;     if (above > NC-1) above = NC-1;
        float cb = cdf[below], ca = cdf[above];
        float bb = dc[below],  ba = dc[above];
        float den = ca - cb;
        den = (den < 1e-5f) ? 1.0f : den;
        fval[q] = bb + ((uu - cb) / den) * (ba - bb);
    }
    __syncthreads();

    // rank-sort the 128 fine depths (ties broken by original index)
    for (int q = t; q < NF; q += 64) {
        float f = fval[q];
        int rank = 0;
        for (int i = 0; i < NF; ++i) {
            float o = fval[i];
            rank += (o < f) || (o == f && i < q);
        }
        fsort[rank] = f;
    }
    __syncthreads();

    // merge coarse (sorted) + fsort (sorted); ties: coarse before fine
    if (t < NC) {
        float c = dc[t];
        int cnt = 0;
        for (int i = 0; i < NF; ++i) cnt += (fsort[i] < c);
        g_dall[r*NA + t + cnt] = c;
    }
    for (int q = t; q < NF; q += 64) {
        float f = fsort[q];
        int cnt = 0;
        for (int i = 0; i < NC; ++i) cnt += (dc[i] <= f);
        g_dall[r*NA + q + cnt] = f;
    }
}

// ---------------------------------------------------------------------------
// K5: 1 - sum(sdf_to_w(sdf_all)) per ray
// ---------------------------------------------------------------------------
__global__ void finish_kernel(float* __restrict__ out) {
    int r = blockIdx.x * blockDim.x + threadIdx.x;
    if (r >= NR) return;
    const float* sp = g_sdfa + r*NA;
    float prev = 1.0f / (1.0f + expf(-100.0f * sp[0]));
    float T = 1.0f, occ = 0.0f;
    for (int i = 1; i < NA; ++i) {
        float cur = 1.0f / (1.0f + expf(-100.0f * sp[i]));
        float a = fmaxf((prev - cur) / (prev + 1e-10f), 0.0f);
        occ = fmaf(a, T, occ);
        T *= (1.0f - a + 1e-10f);
        prev = cur;
    }
    out[r] = 1.0f - occ;
}

// ---------------------------------------------------------------------------
// launch
// ---------------------------------------------------------------------------
extern "C" void kernel_launch(void* const* d_in, const int* in_sizes, int n_in,
                              void* d_out, int out_size) {
    const float* pts   = (const float*)d_in[0];
    const float* light = (const float*)d_in[1];
    const float* u     = (const float*)d_in[2];
    const float* w0    = (const float*)d_in[3];
    const float* b0    = (const float*)d_in[4];
    const float* w1    = (const float*)d_in[5];
    const float* b1    = (const float*)d_in[6];
    const float* w2    = (const float*)d_in[7];
    const float* b2    = (const float*)d_in[8];
    const float* w3    = (const float*)d_in[9];
    const float* b3    = (const float*)d_in[10];
    float* out = (float*)d_out;

    int nsm = 148;
    cudaDeviceGetAttribute(&nsm, cudaDevAttrMultiProcessorCount, 0);

    cudaFuncSetAttribute(mlp_kernel<NC, true>,
                         cudaFuncAttributeMaxDynamicSharedMemorySize, SMEM_BYTES);
    cudaFuncSetAttribute(mlp_kernel<NA, false>,
                         cudaFuncAttributeMaxDynamicSharedMemorySize, SMEM_BYTES);

    prep_kernel<<<NR, 128>>>(pts, light, w0, b0);
    mlp_kernel<NC, true><<<nsm, 256, SMEM_BYTES>>>(w1, b1, w2, b2, w3, b3);
    sample_kernel<<<NR, 64>>>(u);
    mlp_kernel<NA, false><<<nsm, 256, SMEM_BYTES>>>(w1, b1, w2, b2, w3, b3);
    finish_kernel<<<(NR + 127) / 128, 128>>>(out);
}

// round 11
// speedup vs baseline: 1.0013x; 1.0013x over previous
#include <cuda_runtime.h>
#include <math.h>

// ---------------------------------------------------------------------------
// Problem constants
// ---------------------------------------------------------------------------
#define NL 8
#define NP 512
#define NR (NL*NP)          // 4096 rays
#define NC 64               // coarse samples
#define NF 128              // fine samples
#define NA (NC+NF)          // 192 all samples
#define HID 128
#define TILE 128            // samples per MLP tile
#define BUFPAD 132          // padded row length of activation buffer (16B aligned rows)

// scratch (device globals; no allocation allowed)
__device__ float g_u0[NR*HID];       // W0^T pt + b0 per ray
__device__ float g_v0[NR*HID];       // W0^T dir per ray
__device__ float g_sdfc[NR*NC];      // coarse sdf
__device__ float g_dall[NR*NA];      // sorted merged depths
__device__ float g_sdfa[NR*NA];      // fine-pass sdf

// ---------------------------------------------------------------------------
// f32x2 packed helpers (Blackwell FFMA2 — 2x fp32 fma throughput)
// ---------------------------------------------------------------------------
__device__ __forceinline__ unsigned long long pack2(float x) {
    unsigned long long r;
    asm("mov.b64 %0, {%1, %1};" : "=l"(r) : "f"(x));
    return r;
}
__device__ __forceinline__ void ffma2(unsigned long long& d,
                                      unsigned long long a,
                                      unsigned long long b) {
    asm("fma.rn.f32x2 %0, %1, %2, %0;" : "+l"(d) : "l"(a), "l"(b));
}
__device__ __forceinline__ float2 unpack2(unsigned long long v) {
    float lo, hi;
    asm("mov.b64 {%0, %1}, %2;" : "=f"(lo), "=f"(hi) : "l"(v));
    return make_float2(lo, hi);
}

// ---------------------------------------------------------------------------
// K1: per-ray prep — dir normalize + fold layer0 into (u0, v0)
//     h0(sample) = relu(u0 + d * v0)
// ---------------------------------------------------------------------------
__global__ void prep_kernel(const float* __restrict__ pts,
                            const float* __restrict__ light,
                            const float* __restrict__ w0,
                            const float* __restrict__ b0) {
    int r = blockIdx.x;          // ray = l*512 + p
    int k = threadIdx.x;         // hidden unit
    int l = r >> 9, p = r & 511;
    __shared__ float sp[3], sd[3];
    if (k == 0) {
        float px = pts[p*3+0], py = pts[p*3+1], pz = pts[p*3+2];
        float dx = light[l*3+0]-px, dy = light[l*3+1]-py, dz = light[l*3+2]-pz;
        float n = sqrtf(dx*dx + dy*dy + dz*dz);
        sp[0]=px; sp[1]=py; sp[2]=pz;
        sd[0]=dx/n; sd[1]=dy/n; sd[2]=dz/n;
    }
    __syncthreads();
    float w0k = w0[k], w1k = w0[128+k], w2k = w0[256+k];
    float u0 = b0[k] + sp[0]*w0k + sp[1]*w1k + sp[2]*w2k;
    float v0 =         sd[0]*w0k + sd[1]*w1k + sd[2]*w2k;
    g_u0[r*HID + k] = u0;
    g_v0[r*HID + k] = v0;
}

// ---------------------------------------------------------------------------
// Dense 128->128 layer on a 128-sample tile (relu + bias), in-place in smem.
// buf layout: [k (128)][BUFPAD], samples contiguous in the row.
// thread (j,g): output unit j, points [g*64, g*64+64) as 32 f32x2 accs.
// ---------------------------------------------------------------------------
__device__ __forceinline__ void dense_layer(const float* __restrict__ Ws,
                                            const float* __restrict__ bs,
                                            float* __restrict__ buf,
                                            int j, int g) {
    unsigned long long acc[32];
#pragma unroll
    for (int t = 0; t < 32; ++t) acc[t] = 0ULL;

#pragma unroll 4
    for (int k = 0; k < 128; ++k) {
        unsigned long long wv = pack2(Ws[k*128 + j]);           // conflict-free LDS
        const ulonglong2* h4 =
            reinterpret_cast<const ulonglong2*>(buf + k*BUFPAD + g*64); // broadcast LDS.128
#pragma unroll
        for (int t = 0; t < 16; ++t) {
            ulonglong2 hv = h4[t];
            ffma2(acc[2*t+0], hv.x, wv);
            ffma2(acc[2*t+1], hv.y, wv);
        }
    }
    __syncthreads();   // all reads of buf done
    float bj = bs[j];
    float2* outp = reinterpret_cast<float2*>(buf + j*BUFPAD + g*64);
#pragma unroll
    for (int t = 0; t < 32; ++t) {
        float2 v = unpack2(acc[t]);
        v.x = fmaxf(v.x + bj, 0.0f);
        v.y = fmaxf(v.y + bj, 0.0f);
        outp[t] = v;
    }
    __syncthreads();   // buf now holds layer output
}

// ---------------------------------------------------------------------------
// K2/K4: fused 3-layer MLP over all samples. Persistent CTAs, weights in smem.
// COARSE: d analytic, out -> g_sdfc.  else: d from g_dall, out -> g_sdfa.
// ---------------------------------------------------------------------------
// smem floats: W1(16384) W2(16384) buf(128*132=16896) b1(128) b2(128) w3(128) d(128)
#define SMEM_FLOATS (16384*2 + 128*BUFPAD + 128*4)
#define SMEM_BYTES  (SMEM_FLOATS * 4)

template <int M, bool COARSE>
__global__ void __launch_bounds__(256, 1)
mlp_kernel(const float* __restrict__ w1, const float* __restrict__ b1,
           const float* __restrict__ w2, const float* __restrict__ b2,
           const float* __restrict__ w3, const float* __restrict__ b3) {
    extern __shared__ float sm[];
    float* W1s = sm;
    float* W2s = sm + 16384;
    float* buf = sm + 32768;
    float* b1s = sm + 32768 + 128*BUFPAD;
    float* b2s = b1s + 128;
    float* w3s = b2s + 128;
    float* d_s = w3s + 128;

    const int tid = threadIdx.x;
    const int j = tid & 127;
    const int g = tid >> 7;

    // load weights once per CTA (persistent)
    {
        const float4* s1 = reinterpret_cast<const float4*>(w1);
        const float4* s2 = reinterpret_cast<const float4*>(w2);
        float4* dd1 = reinterpret_cast<float4*>(W1s);
        float4* dd2 = reinterpret_cast<float4*>(W2s);
        for (int i = tid; i < 4096; i += 256) { dd1[i] = s1[i]; dd2[i] = s2[i]; }
        if (tid < 128) { b1s[tid] = b1[tid]; b2s[tid] = b2[tid]; w3s[tid] = w3[tid]; }
    }
    const float b3v = b3[0];
    __syncthreads();

    const int ntiles = (NR * M) / TILE;   // exact, no tail
    for (int tile = blockIdx.x; tile < ntiles; tile += gridDim.x) {
        const int s0 = tile * TILE;

        // stage depths for the tile
        if (tid < TILE) {
            int s = s0 + tid;
            float dv;
            if (COARSE) {
                int m = s & (NC - 1);
                float tt = (float)m * (1.0f / (float)NC);
                dv = 1e-3f * (1.0f - tt) + 0.5f * tt;
            } else {
                dv = g_dall[s];
            }
            d_s[tid] = dv;
        }

        // a tile spans at most 2 rays
        int ray0 = s0 / M;
        int ray1 = (s0 + TILE - 1) / M;
        int split = (ray1 == ray0) ? TILE : (ray1 * M - s0);
        float u0a = g_u0[ray0*HID + j], v0a = g_v0[ray0*HID + j];
        float u0b = g_u0[ray1*HID + j], v0b = g_v0[ray1*HID + j];
        __syncthreads();

        // h0 = relu(u0 + d*v0)
        float* myrow = buf + j*BUFPAD + g*64;
#pragma unroll 8
        for (int bb = 0; bb < 64; ++bb) {
            int b = g*64 + bb;
            float uu = (b < split) ? u0a : u0b;
            float vv = (b < split) ? v0a : v0b;
            myrow[bb] = fmaxf(fmaf(d_s[b], vv, uu), 0.0f);
        }
        __syncthreads();

        dense_layer(W1s, b1s, buf, j, g);
        dense_layer(W2s, b2s, buf, j, g);

        // layer 3: 128->1 per sample
        if (tid < TILE) {
            float a3 = 0.0f;
#pragma unroll 16
            for (int k = 0; k < 128; ++k)
                a3 = fmaf(buf[k*BUFPAD + tid], w3s[k], a3);
            float* outp = COARSE ? g_sdfc : g_sdfa;
            outp[s0 + tid] = a3 + b3v;
        }
        __syncthreads();   // protect buf before next tile's h0
    }
}

// ---------------------------------------------------------------------------
// K3: per-ray weights -> pdf sampling -> rank-sort fine -> merge with coarse
// ---------------------------------------------------------------------------
__global__ void sample_kernel(const float* __restrict__ u_in) {
    int r = blockIdx.x;
    int t = threadIdx.x;   // 64 threads
    __shared__ float sig[NC], cdf[NC], dc[NC], w63[NC-1];
    __shared__ float fval[NF], fsort[NF];

    if (t < NC) {
        float sdf = g_sdfc[r*NC + t];
        sig[t] = 1.0f / (1.0f + expf(-100.0f * sdf));
        float tt = (float)t * (1.0f / (float)NC);
        dc[t] = 1e-3f * (1.0f - tt) + 0.5f * tt;
    }
    __syncthreads();

    if (t == 0) {
        // sdf_to_w + (+1e-5) + sum (serial, 63 steps)
        float T = 1.0f, wsum = 0.0f;
        for (int i = 0; i < NC-1; ++i) {
            float a = fmaxf((sig[i] - sig[i+1]) / (sig[i] + 1e-10f), 0.0f);
            float wv = a * T + 1e-5f;
            w63[i] = wv;
            wsum += wv;
            T *= (1.0f - a + 1e-10f);
        }
        float c = 0.0f;
        cdf[0] = 0.0f;
        for (int i = 0; i < NC-1; ++i) {
            c += w63[i] / wsum;
            cdf[i+1] = c;
        }
    }
    __syncthreads();

    // inverse-CDF sampling: 2 u's per thread
    for (int q = t; q < NF; q += 64) {
        float uu = u_in[r*NF + q];
        int inds = 0;
#pragma unroll
        for (int i = 0; i < NC; ++i) inds += (uu >= cdf[i]) ? 1 : 0;
        int below = inds - 1; if (below < 0) below = 0; if (below > NC-1) below = NC-1;
        int above = inds;     if (above > NC-1) above = NC-1;
        float cb = cdf[below], ca = cdf[above];
        float bb = dc[below],  ba = dc[above];
        float den = ca - cb;
        den = (den < 1e-5f) ? 1.0f : den;
        fval[q] = bb + ((uu - cb) / den) * (ba - bb);
    }
    __syncthreads();

    // rank-sort the 128 fine depths (ties broken by original index)
    for (int q = t; q < NF; q += 64) {
        float f = fval[q];
        int rank = 0;
        for (int i = 0; i < NF; ++i) {
            float o = fval[i];
            rank += (o < f) || (o == f && i < q);
        }
        fsort[rank] = f;
    }
    __syncthreads();

    // merge coarse (sorted) + fsort (sorted); ties: coarse before fine
    if (t < NC) {
        float c = dc[t];
        int cnt = 0;
        for (int i = 0; i < NF; ++i) cnt += (fsort[i] < c);
        g_dall[r*NA + t + cnt] = c;
    }
    for (int q = t; q < NF; q += 64) {
        float f = fsort[q];
        int cnt = 0;
        for (int i = 0; i < NC; ++i) cnt += (dc[i] <= f);
        g_dall[r*NA + q + cnt] = f;
    }
}

// ---------------------------------------------------------------------------
// K5: 1 - sum(sdf_to_w(sdf_all)) per ray
// ---------------------------------------------------------------------------
__global__ void finish_kernel(float* __restrict__ out) {
    int r = blockIdx.x * blockDim.x + threadIdx.x;
    if (r >= NR) return;
    const float* sp = g_sdfa + r*NA;
    float prev = 1.0f / (1.0f + expf(-100.0f * sp[0]));
    float T = 1.0f, occ = 0.0f;
    for (int i = 1; i < NA; ++i) {
        float cur = 1.0f / (1.0f + expf(-100.0f * sp[i]));
        float a = fmaxf((prev - cur) / (prev + 1e-10f), 0.0f);
        occ = fmaf(a, T, occ);
        T *= (1.0f - a + 1e-10f);
        prev = cur;
    }
    out[r] = 1.0f - occ;
}

// ---------------------------------------------------------------------------
// launch
// ---------------------------------------------------------------------------
extern "C" void kernel_launch(void* const* d_in, const int* in_sizes, int n_in,
                              void* d_out, int out_size) {
    const float* pts   = (const float*)d_in[0];
    const float* light = (const float*)d_in[1];
    const float* u     = (const float*)d_in[2];
    const float* w0    = (const float*)d_in[3];
    const float* b0    = (const float*)d_in[4];
    const float* w1    = (const float*)d_in[5];
    const float* b1    = (const float*)d_in[6];
    const float* w2    = (const float*)d_in[7];
    const float* b2    = (const float*)d_in[8];
    const float* w3    = (const float*)d_in[9];
    const float* b3    = (const float*)d_in[10];
    float* out = (float*)d_out;

    int nsm = 148;
    cudaDeviceGetAttribute(&nsm, cudaDevAttrMultiProcessorCount, 0);

    cudaFuncSetAttribute(mlp_kernel<NC, true>,
                         cudaFuncAttributeMaxDynamicSharedMemorySize, SMEM_BYTES);
    cudaFuncSetAttribute(mlp_kernel<NA, false>,
                         cudaFuncAttributeMaxDynamicSharedMemorySize, SMEM_BYTES);

    prep_kernel<<<NR, 128>>>(pts, light, w0, b0);
    mlp_kernel<NC, true><<<nsm, 256, SMEM_BYTES>>>(w1, b1, w2, b2, w3, b3);
    sample_kernel<<<NR, 64>>>(u);
    mlp_kernel<NA, false><<<nsm, 256, SMEM_BYTES>>>(w1, b1, w2, b2, w3, b3);
    finish_kernel<<<(NR + 127) / 128, 128>>>(out);
}